// round 1
// baseline (speedup 1.0000x reference)
#include <cuda_runtime.h>
#include <math.h>

#define B   4
#define S   2048
#define H   768
#define NH  12
#define DH  64
#define WH  128
#define TOK (B*S)
#define EPS 1e-12f

// ---------------- scratch (device globals; no allocation allowed) ----------------
__device__ float g_Q[(size_t)TOK*H];
__device__ float g_K[(size_t)TOK*H];
__device__ float g_V[(size_t)TOK*H];
__device__ float g_ctx[(size_t)TOK*H];
__device__ float g_proj[(size_t)TOK*H];
__device__ float g_gates[(size_t)TOK*NH];

// ---------------- 128x128x16 SGEMM:  C[M,N] = A[M,K] @ W[K,N] + bias ----------------
#define BM 128
#define BN 128
#define BK 16

__global__ __launch_bounds__(256) void sgemm_bias(const float* __restrict__ A,
                                                  const float* __restrict__ Wm,
                                                  const float* __restrict__ bias,
                                                  float* __restrict__ C,
                                                  int M, int N, int K)
{
    __shared__ float As[BK][BM];
    __shared__ float Bs[BK][BN];
    const int t  = threadIdx.x;
    const int m0 = blockIdx.y * BM;
    const int n0 = blockIdx.x * BN;
    const int ty = t / 16;      // 0..15
    const int tx = t % 16;      // 0..15

    float acc[8][8];
#pragma unroll
    for (int i = 0; i < 8; i++)
#pragma unroll
        for (int j = 0; j < 8; j++) acc[i][j] = 0.f;

    for (int k0 = 0; k0 < K; k0 += BK) {
        // A tile 128x16 -> As[k][m] (transposed)
#pragma unroll
        for (int i = 0; i < 2; i++) {
            int id  = t * 2 + i;            // 0..511
            int row = id >> 2;              // 0..127
            int c4  = (id & 3) * 4;         // 0,4,8,12
            float4 v = *(const float4*)&A[(size_t)(m0 + row) * K + k0 + c4];
            As[c4 + 0][row] = v.x;
            As[c4 + 1][row] = v.y;
            As[c4 + 2][row] = v.z;
            As[c4 + 3][row] = v.w;
        }
        // B tile 16x128
#pragma unroll
        for (int i = 0; i < 2; i++) {
            int id = t * 2 + i;             // 0..511
            int kk = id >> 5;               // 0..15
            int c4 = (id & 31) * 4;         // 0..124
            *(float4*)&Bs[kk][c4] = *(const float4*)&Wm[(size_t)(k0 + kk) * N + n0 + c4];
        }
        __syncthreads();

#pragma unroll
        for (int kk = 0; kk < BK; kk++) {
            float a[8], bb[8];
            *(float4*)&a[0]  = *(float4*)&As[kk][ty * 4];
            *(float4*)&a[4]  = *(float4*)&As[kk][64 + ty * 4];
            *(float4*)&bb[0] = *(float4*)&Bs[kk][tx * 4];
            *(float4*)&bb[4] = *(float4*)&Bs[kk][64 + tx * 4];
#pragma unroll
            for (int i = 0; i < 8; i++)
#pragma unroll
                for (int j = 0; j < 8; j++) acc[i][j] += a[i] * bb[j];
        }
        __syncthreads();
    }

#pragma unroll
    for (int i = 0; i < 8; i++) {
        int row = m0 + ((i < 4) ? (ty * 4 + i) : (64 + ty * 4 + (i - 4)));
#pragma unroll
        for (int jh = 0; jh < 2; jh++) {
            int col = n0 + ((jh == 0) ? (tx * 4) : (64 + tx * 4));
            float4 v;
            v.x = acc[i][jh * 4 + 0] + bias[col + 0];
            v.y = acc[i][jh * 4 + 1] + bias[col + 1];
            v.z = acc[i][jh * 4 + 2] + bias[col + 2];
            v.w = acc[i][jh * 4 + 3] + bias[col + 3];
            *(float4*)&C[(size_t)row * N + col] = v;
        }
    }
}

// ---------------- gate MLP: g = sigmoid(relu(LN(X@Wg1+bg1)) @ Wg2 + bg2) ----------------
#define GTOK 8
__global__ __launch_bounds__(128) void gate_kernel(const float* __restrict__ X,
                                                   const float* __restrict__ Wg1,
                                                   const float* __restrict__ bg1,
                                                   const float* __restrict__ glnw,
                                                   const float* __restrict__ glnb,
                                                   const float* __restrict__ Wg2,
                                                   const float* __restrict__ bg2,
                                                   float* __restrict__ gates)
{
    __shared__ float xs[GTOK][H];
    __shared__ float gs[GTOK][WH];
    __shared__ float mu_s[GTOK], iv_s[GTOK];
    const int t    = threadIdx.x;        // 0..127 == output channel j
    const int tok0 = blockIdx.x * GTOK;

    for (int id = t; id < GTOK * (H / 4); id += 128) {
        int r = id / (H / 4);
        int c = id % (H / 4);
        *(float4*)&xs[r][c * 4] = *(const float4*)&X[(size_t)(tok0 + r) * H + c * 4];
    }
    __syncthreads();

    float acc[GTOK];
    float b0 = bg1[t];
#pragma unroll
    for (int r = 0; r < GTOK; r++) acc[r] = b0;

#pragma unroll 4
    for (int k = 0; k < H; k++) {
        float w = Wg1[(size_t)k * WH + t];
#pragma unroll
        for (int r = 0; r < GTOK; r++) acc[r] += xs[r][k] * w;
    }
#pragma unroll
    for (int r = 0; r < GTOK; r++) gs[r][t] = acc[r];
    __syncthreads();

    // LN over 128 per token
    int w = t >> 5, ln = t & 31;
    for (int r = w; r < GTOK; r += 4) {
        float s = 0.f, sq = 0.f;
#pragma unroll
        for (int i = 0; i < 4; i++) {
            float v = gs[r][ln + 32 * i];
            s += v; sq += v * v;
        }
        for (int o = 16; o; o >>= 1) {
            s  += __shfl_xor_sync(0xffffffffu, s, o);
            sq += __shfl_xor_sync(0xffffffffu, sq, o);
        }
        if (ln == 0) {
            float mu = s * (1.f / WH);
            mu_s[r] = mu;
            iv_s[r] = rsqrtf(sq * (1.f / WH) - mu * mu + EPS);
        }
    }
    __syncthreads();
    float gw = glnw[t], gb = glnb[t];
#pragma unroll
    for (int r = 0; r < GTOK; r++) {
        float y = (gs[r][t] - mu_s[r]) * iv_s[r] * gw + gb;
        gs[r][t] = fmaxf(y, 0.f);
    }
    __syncthreads();

    if (t < GTOK * NH) {
        int r  = t / NH;
        int hh = t % NH;
        float s = bg2[hh];
#pragma unroll 4
        for (int k = 0; k < WH; k++) s += gs[r][k] * Wg2[k * NH + hh];
        gates[(size_t)(tok0 + r) * NH + hh] = 1.f / (1.f + __expf(-s));
    }
}

// ---------------- fused attention: scores -> softmax -> probs out -> PV ----------------
#define QT  16
#define KT  64
#define KVP 76   // padded key/value row (float4-aligned, low-conflict)

__global__ __launch_bounds__(512) void attn_kernel(const float* __restrict__ am,
                                                   float* __restrict__ probs)
{
    extern __shared__ float sm[];
    float* sc  = sm;                       // QT*S
    float* Ks  = sc  + QT * S;             // KT*KVP  (reused for V)
    float* Qs  = Ks  + KT * KVP;           // QT*64
    float* msk = Qs  + QT * 64;            // S
    float* gt  = msk + S;                  // QT

    const int t  = threadIdx.x;
    const int qt = blockIdx.x;
    const int h  = blockIdx.y;
    const int b  = blockIdx.z;
    const int q0 = qt * QT;

    const float* Qg = g_Q + ((size_t)(b * S + q0)) * H + h * DH;
    if (t < 256) {
        int qr = t / 16, d4 = (t % 16) * 4;
        *(float4*)&Qs[qr * 64 + d4] = *(const float4*)&Qg[(size_t)qr * H + d4];
    }
    for (int j = t; j < S; j += 512) msk[j] = (1.f - am[(size_t)b * S + j]) * -10000.f;
    if (t < QT) gt[t] = g_gates[(size_t)(b * S + q0 + t) * NH + h] * 0.125f; // fold 1/sqrt(DH)
    __syncthreads();

    const int kc = t % 64;
    const int qg = t / 64;                 // 0..7, rows {2qg, 2qg+1}

    // ---- scores: sc[r][col] = gate[r]*(q.k)/8 + mask[col] ----
    for (int kt = 0; kt < S / KT; kt++) {
        const int kb = kt * KT;
        __syncthreads();
        const float* Kg = g_K + ((size_t)(b * S + kb)) * H + h * DH;
#pragma unroll
        for (int i = 0; i < 2; i++) {
            int id = t + i * 512;          // 0..1023
            int r = id / 16, d4 = (id % 16) * 4;
            *(float4*)&Ks[r * KVP + d4] = *(const float4*)&Kg[(size_t)r * H + d4];
        }
        __syncthreads();

        float a0 = 0.f, a1 = 0.f;
#pragma unroll
        for (int d = 0; d < DH; d += 4) {
            float4 kv  = *(float4*)&Ks[kc * KVP + d];
            float4 q0v = *(float4*)&Qs[(qg * 2 + 0) * 64 + d];
            float4 q1v = *(float4*)&Qs[(qg * 2 + 1) * 64 + d];
            a0 += q0v.x * kv.x + q0v.y * kv.y + q0v.z * kv.z + q0v.w * kv.w;
            a1 += q1v.x * kv.x + q1v.y * kv.y + q1v.z * kv.z + q1v.w * kv.w;
        }
        int col = kb + kc;
        sc[(qg * 2 + 0) * S + col] = a0 * gt[qg * 2 + 0] + msk[col];
        sc[(qg * 2 + 1) * S + col] = a1 * gt[qg * 2 + 1] + msk[col];
    }
    __syncthreads();

    // ---- softmax: one warp per query row, write probs ----
    {
        int wid = t >> 5, ln = t & 31;     // wid 0..15 = row
        float* row = sc + (size_t)wid * S;
        float m = -1e30f;
        for (int j = ln; j < S; j += 32) m = fmaxf(m, row[j]);
        for (int o = 16; o; o >>= 1) m = fmaxf(m, __shfl_xor_sync(0xffffffffu, m, o));
        float ssum = 0.f;
        for (int j = ln; j < S; j += 32) {
            float e = __expf(row[j] - m);
            row[j] = e;
            ssum += e;
        }
        for (int o = 16; o; o >>= 1) ssum += __shfl_xor_sync(0xffffffffu, ssum, o);
        float inv = 1.f / ssum;
        float* pout = probs + (((size_t)b * NH + h) * S + (q0 + wid)) * S;
        for (int j = ln; j < S; j += 32) {
            float p = row[j] * inv;
            row[j] = p;
            pout[j] = p;
        }
    }
    __syncthreads();

    // ---- PV: ctx[r][d] = sum_j p[r][j] * V[j][d] ----
    const int d = t % 64;
    float c0 = 0.f, c1 = 0.f;
    for (int kt = 0; kt < S / KT; kt++) {
        const int kb = kt * KT;
        __syncthreads();
        const float* Vg = g_V + ((size_t)(b * S + kb)) * H + h * DH;
#pragma unroll
        for (int i = 0; i < 2; i++) {
            int id = t + i * 512;
            int r = id / 16, d4 = (id % 16) * 4;
            *(float4*)&Ks[r * KVP + d4] = *(const float4*)&Vg[(size_t)r * H + d4];
        }
        __syncthreads();

#pragma unroll 4
        for (int j4 = 0; j4 < KT; j4 += 4) {
            float4 p0 = *(float4*)&sc[(qg * 2 + 0) * S + kb + j4];
            float4 p1 = *(float4*)&sc[(qg * 2 + 1) * S + kb + j4];
            float v0 = Ks[(j4 + 0) * KVP + d];
            float v1 = Ks[(j4 + 1) * KVP + d];
            float v2 = Ks[(j4 + 2) * KVP + d];
            float v3 = Ks[(j4 + 3) * KVP + d];
            c0 += p0.x * v0 + p0.y * v1 + p0.z * v2 + p0.w * v3;
            c1 += p1.x * v0 + p1.y * v1 + p1.z * v2 + p1.w * v3;
        }
    }
    g_ctx[(size_t)(b * S + q0 + qg * 2 + 0) * H + h * DH + d] = c0;
    g_ctx[(size_t)(b * S + q0 + qg * 2 + 1) * H + h * DH + d] = c1;
}

// ---------------- residual + LayerNorm(768) ----------------
__global__ __launch_bounds__(256) void ln_kernel(const float* __restrict__ P,
                                                 const float* __restrict__ Xres,
                                                 const float* __restrict__ w,
                                                 const float* __restrict__ bb,
                                                 float* __restrict__ out)
{
    const int tok = blockIdx.x;
    const int t   = threadIdx.x;
    __shared__ float rs[8], rq[8];
    __shared__ float smu, siv;

    float v[3];
    float s = 0.f, sq = 0.f;
#pragma unroll
    for (int i = 0; i < 3; i++) {
        int c = t + i * 256;
        float x = P[(size_t)tok * H + c] + Xres[(size_t)tok * H + c];
        v[i] = x; s += x; sq += x * x;
    }
    for (int o = 16; o; o >>= 1) {
        s  += __shfl_xor_sync(0xffffffffu, s, o);
        sq += __shfl_xor_sync(0xffffffffu, sq, o);
    }
    int wi = t >> 5, ln = t & 31;
    if (ln == 0) { rs[wi] = s; rq[wi] = sq; }
    __syncthreads();
    if (t == 0) {
        float ts = 0.f, tq = 0.f;
#pragma unroll
        for (int i = 0; i < 8; i++) { ts += rs[i]; tq += rq[i]; }
        float mu = ts * (1.f / H);
        smu = mu;
        siv = rsqrtf(tq * (1.f / H) - mu * mu + EPS);
    }
    __syncthreads();
    float mu = smu, iv = siv;
#pragma unroll
    for (int i = 0; i < 3; i++) {
        int c = t + i * 256;
        out[(size_t)tok * H + c] = (v[i] - mu) * iv * w[c] + bb[c];
    }
}

// ---------------- launch ----------------
extern "C" void kernel_launch(void* const* d_in, const int* in_sizes, int n_in,
                              void* d_out, int out_size)
{
    const float* X    = (const float*)d_in[0];
    const float* am   = (const float*)d_in[1];
    const float* Wq   = (const float*)d_in[2];
    const float* bq   = (const float*)d_in[3];
    const float* Wk   = (const float*)d_in[4];
    const float* bk   = (const float*)d_in[5];
    const float* Wv   = (const float*)d_in[6];
    const float* bv   = (const float*)d_in[7];
    const float* Wg1  = (const float*)d_in[8];
    const float* bg1  = (const float*)d_in[9];
    const float* glnw = (const float*)d_in[10];
    const float* glnb = (const float*)d_in[11];
    const float* Wg2  = (const float*)d_in[12];
    const float* bg2  = (const float*)d_in[13];
    const float* Wo   = (const float*)d_in[14];
    const float* bo   = (const float*)d_in[15];
    const float* lnw  = (const float*)d_in[16];
    const float* lnb  = (const float*)d_in[17];

    float* out   = (float*)d_out;
    float* probs = out + (size_t)B * S * H;

    float *Qp, *Kp, *Vp, *Cp, *Pp;
    cudaGetSymbolAddress((void**)&Qp, g_Q);
    cudaGetSymbolAddress((void**)&Kp, g_K);
    cudaGetSymbolAddress((void**)&Vp, g_V);
    cudaGetSymbolAddress((void**)&Cp, g_ctx);
    cudaGetSymbolAddress((void**)&Pp, g_proj);

    dim3 ggemm(H / BN, TOK / BM);
    sgemm_bias<<<ggemm, 256>>>(X, Wq, bq, Qp, TOK, H, H);
    sgemm_bias<<<ggemm, 256>>>(X, Wk, bk, Kp, TOK, H, H);
    sgemm_bias<<<ggemm, 256>>>(X, Wv, bv, Vp, TOK, H, H);

    {
        float* Gp;
        cudaGetSymbolAddress((void**)&Gp, g_gates);
        gate_kernel<<<TOK / GTOK, 128>>>(X, Wg1, bg1, glnw, glnb, Wg2, bg2, Gp);
    }

    size_t att_smem = (size_t)(QT * S + KT * KVP + QT * 64 + S + QT) * sizeof(float);
    cudaFuncSetAttribute(attn_kernel, cudaFuncAttributeMaxDynamicSharedMemorySize, (int)att_smem);
    dim3 gatt(S / QT, NH, B);
    attn_kernel<<<gatt, 512, att_smem>>>(am, probs);

    sgemm_bias<<<ggemm, 256>>>(Cp, Wo, bo, Pp, TOK, H, H);

    ln_kernel<<<TOK, 256>>>(Pp, X, lnw, lnb, out);
}

// round 2
// speedup vs baseline: 1.0146x; 1.0146x over previous
#include <cuda_runtime.h>
#include <math.h>

#define B   4
#define S   2048
#define H   768
#define NH  12
#define DH  64
#define WH  128
#define TOK (B*S)
#define EPS 1e-12f

// ---------------- scratch (device globals; no allocation allowed) ----------------
__device__ float g_Q[(size_t)TOK*H];
__device__ float g_K[(size_t)TOK*H];
__device__ float g_V[(size_t)TOK*H];
__device__ float g_ctx[(size_t)TOK*H];
__device__ float g_proj[(size_t)TOK*H];
__device__ float g_gates[(size_t)TOK*NH];

// ---------------- 128x128x16 SGEMM:  C[M,N] = A[M,K] @ W[K,N] + bias ----------------
#define BM 128
#define BN 128
#define BK 16

__global__ __launch_bounds__(256) void sgemm_bias(const float* __restrict__ A,
                                                  const float* __restrict__ Wm,
                                                  const float* __restrict__ bias,
                                                  float* __restrict__ C,
                                                  int M, int N, int K)
{
    __shared__ float As[BK][BM];
    __shared__ float Bs[BK][BN];
    const int t  = threadIdx.x;
    const int m0 = blockIdx.y * BM;
    const int n0 = blockIdx.x * BN;
    const int ty = t / 16;      // 0..15
    const int tx = t % 16;      // 0..15

    float acc[8][8];
#pragma unroll
    for (int i = 0; i < 8; i++)
#pragma unroll
        for (int j = 0; j < 8; j++) acc[i][j] = 0.f;

    for (int k0 = 0; k0 < K; k0 += BK) {
        // A tile 128x16 -> As[k][m] (transposed)
#pragma unroll
        for (int i = 0; i < 2; i++) {
            int id  = t * 2 + i;            // 0..511
            int row = id >> 2;              // 0..127
            int c4  = (id & 3) * 4;         // 0,4,8,12
            float4 v = *(const float4*)&A[(size_t)(m0 + row) * K + k0 + c4];
            As[c4 + 0][row] = v.x;
            As[c4 + 1][row] = v.y;
            As[c4 + 2][row] = v.z;
            As[c4 + 3][row] = v.w;
        }
        // B tile 16x128
#pragma unroll
        for (int i = 0; i < 2; i++) {
            int id = t * 2 + i;             // 0..511
            int kk = id >> 5;               // 0..15
            int c4 = (id & 31) * 4;         // 0..124
            *(float4*)&Bs[kk][c4] = *(const float4*)&Wm[(size_t)(k0 + kk) * N + n0 + c4];
        }
        __syncthreads();

#pragma unroll
        for (int kk = 0; kk < BK; kk++) {
            float a[8], bb[8];
            *(float4*)&a[0]  = *(float4*)&As[kk][ty * 4];
            *(float4*)&a[4]  = *(float4*)&As[kk][64 + ty * 4];
            *(float4*)&bb[0] = *(float4*)&Bs[kk][tx * 4];
            *(float4*)&bb[4] = *(float4*)&Bs[kk][64 + tx * 4];
#pragma unroll
            for (int i = 0; i < 8; i++)
#pragma unroll
                for (int j = 0; j < 8; j++) acc[i][j] += a[i] * bb[j];
        }
        __syncthreads();
    }

#pragma unroll
    for (int i = 0; i < 8; i++) {
        int row = m0 + ((i < 4) ? (ty * 4 + i) : (64 + ty * 4 + (i - 4)));
#pragma unroll
        for (int jh = 0; jh < 2; jh++) {
            int col = n0 + ((jh == 0) ? (tx * 4) : (64 + tx * 4));
            float4 v;
            v.x = acc[i][jh * 4 + 0] + bias[col + 0];
            v.y = acc[i][jh * 4 + 1] + bias[col + 1];
            v.z = acc[i][jh * 4 + 2] + bias[col + 2];
            v.w = acc[i][jh * 4 + 3] + bias[col + 3];
            *(float4*)&C[(size_t)row * N + col] = v;
        }
    }
}

// ---------------- gate MLP: g = sigmoid(relu(LN(X@Wg1+bg1)) @ Wg2 + bg2) ----------------
#define GTOK 8
__global__ __launch_bounds__(128) void gate_kernel(const float* __restrict__ X,
                                                   const float* __restrict__ Wg1,
                                                   const float* __restrict__ bg1,
                                                   const float* __restrict__ glnw,
                                                   const float* __restrict__ glnb,
                                                   const float* __restrict__ Wg2,
                                                   const float* __restrict__ bg2,
                                                   float* __restrict__ gates)
{
    __shared__ float xs[GTOK][H];
    __shared__ float gs[GTOK][WH];
    __shared__ float mu_s[GTOK], iv_s[GTOK];
    const int t    = threadIdx.x;        // 0..127 == output channel j
    const int tok0 = blockIdx.x * GTOK;

    for (int id = t; id < GTOK * (H / 4); id += 128) {
        int r = id / (H / 4);
        int c = id % (H / 4);
        *(float4*)&xs[r][c * 4] = *(const float4*)&X[(size_t)(tok0 + r) * H + c * 4];
    }
    __syncthreads();

    float acc[GTOK];
    float b0 = bg1[t];
#pragma unroll
    for (int r = 0; r < GTOK; r++) acc[r] = b0;

#pragma unroll 4
    for (int k = 0; k < H; k++) {
        float w = Wg1[(size_t)k * WH + t];
#pragma unroll
        for (int r = 0; r < GTOK; r++) acc[r] += xs[r][k] * w;
    }
#pragma unroll
    for (int r = 0; r < GTOK; r++) gs[r][t] = acc[r];
    __syncthreads();

    // LN over 128 per token
    int w = t >> 5, ln = t & 31;
    for (int r = w; r < GTOK; r += 4) {
        float s = 0.f, sq = 0.f;
#pragma unroll
        for (int i = 0; i < 4; i++) {
            float v = gs[r][ln + 32 * i];
            s += v; sq += v * v;
        }
        for (int o = 16; o; o >>= 1) {
            s  += __shfl_xor_sync(0xffffffffu, s, o);
            sq += __shfl_xor_sync(0xffffffffu, sq, o);
        }
        if (ln == 0) {
            float mu = s * (1.f / WH);
            mu_s[r] = mu;
            iv_s[r] = rsqrtf(sq * (1.f / WH) - mu * mu + EPS);
        }
    }
    __syncthreads();
    float gw = glnw[t], gb = glnb[t];
#pragma unroll
    for (int r = 0; r < GTOK; r++) {
        float y = (gs[r][t] - mu_s[r]) * iv_s[r] * gw + gb;
        gs[r][t] = fmaxf(y, 0.f);
    }
    __syncthreads();

    if (t < GTOK * NH) {
        int r  = t / NH;
        int hh = t % NH;
        float s = bg2[hh];
#pragma unroll 4
        for (int k = 0; k < WH; k++) s += gs[r][k] * Wg2[k * NH + hh];
        gates[(size_t)(tok0 + r) * NH + hh] = 1.f / (1.f + __expf(-s));
    }
}

// ---------------- fused attention: scores -> softmax -> probs out -> PV ----------------
#define QT  16
#define KT  64
#define KVP 76   // padded key/value row (float4-aligned, low-conflict)

__global__ __launch_bounds__(512) void attn_kernel(const float* __restrict__ am,
                                                   float* __restrict__ probs)
{
    extern __shared__ float sm[];
    float* sc  = sm;                       // QT*S
    float* Ks  = sc  + QT * S;             // KT*KVP  (reused for V)
    float* Qs  = Ks  + KT * KVP;           // QT*64
    float* msk = Qs  + QT * 64;            // S
    float* gt  = msk + S;                  // QT

    const int t  = threadIdx.x;
    const int qt = blockIdx.x;
    const int h  = blockIdx.y;
    const int b  = blockIdx.z;
    const int q0 = qt * QT;

    const float* Qg = g_Q + ((size_t)(b * S + q0)) * H + h * DH;
    if (t < 256) {
        int qr = t / 16, d4 = (t % 16) * 4;
        *(float4*)&Qs[qr * 64 + d4] = *(const float4*)&Qg[(size_t)qr * H + d4];
    }
    for (int j = t; j < S; j += 512) msk[j] = (1.f - am[(size_t)b * S + j]) * -10000.f;
    if (t < QT) gt[t] = g_gates[(size_t)(b * S + q0 + t) * NH + h] * 0.125f; // fold 1/sqrt(DH)
    __syncthreads();

    const int kc = t % 64;
    const int qg = t / 64;                 // 0..7, rows {2qg, 2qg+1}

    // ---- scores: sc[r][col] = gate[r]*(q.k)/8 + mask[col] ----
    for (int kt = 0; kt < S / KT; kt++) {
        const int kb = kt * KT;
        __syncthreads();
        const float* Kg = g_K + ((size_t)(b * S + kb)) * H + h * DH;
#pragma unroll
        for (int i = 0; i < 2; i++) {
            int id = t + i * 512;          // 0..1023
            int r = id / 16, d4 = (id % 16) * 4;
            *(float4*)&Ks[r * KVP + d4] = *(const float4*)&Kg[(size_t)r * H + d4];
        }
        __syncthreads();

        float a0 = 0.f, a1 = 0.f;
#pragma unroll
        for (int d = 0; d < DH; d += 4) {
            float4 kv  = *(float4*)&Ks[kc * KVP + d];
            float4 q0v = *(float4*)&Qs[(qg * 2 + 0) * 64 + d];
            float4 q1v = *(float4*)&Qs[(qg * 2 + 1) * 64 + d];
            a0 += q0v.x * kv.x + q0v.y * kv.y + q0v.z * kv.z + q0v.w * kv.w;
            a1 += q1v.x * kv.x + q1v.y * kv.y + q1v.z * kv.z + q1v.w * kv.w;
        }
        int col = kb + kc;
        sc[(qg * 2 + 0) * S + col] = a0 * gt[qg * 2 + 0] + msk[col];
        sc[(qg * 2 + 1) * S + col] = a1 * gt[qg * 2 + 1] + msk[col];
    }
    __syncthreads();

    // ---- softmax: one warp per query row, write probs ----
    {
        int wid = t >> 5, ln = t & 31;     // wid 0..15 = row
        float* row = sc + (size_t)wid * S;
        float m = -1e30f;
        for (int j = ln; j < S; j += 32) m = fmaxf(m, row[j]);
        for (int o = 16; o; o >>= 1) m = fmaxf(m, __shfl_xor_sync(0xffffffffu, m, o));
        float ssum = 0.f;
        for (int j = ln; j < S; j += 32) {
            float e = __expf(row[j] - m);
            row[j] = e;
            ssum += e;
        }
        for (int o = 16; o; o >>= 1) ssum += __shfl_xor_sync(0xffffffffu, ssum, o);
        float inv = 1.f / ssum;
        float* pout = probs + (((size_t)b * NH + h) * S + (q0 + wid)) * S;
        for (int j = ln; j < S; j += 32) {
            float p = row[j] * inv;
            row[j] = p;
            pout[j] = p;
        }
    }
    __syncthreads();

    // ---- PV: ctx[r][d] = sum_j p[r][j] * V[j][d] ----
    const int d = t % 64;
    float c0 = 0.f, c1 = 0.f;
    for (int kt = 0; kt < S / KT; kt++) {
        const int kb = kt * KT;
        __syncthreads();
        const float* Vg = g_V + ((size_t)(b * S + kb)) * H + h * DH;
#pragma unroll
        for (int i = 0; i < 2; i++) {
            int id = t + i * 512;
            int r = id / 16, d4 = (id % 16) * 4;
            *(float4*)&Ks[r * KVP + d4] = *(const float4*)&Vg[(size_t)r * H + d4];
        }
        __syncthreads();

#pragma unroll 4
        for (int j4 = 0; j4 < KT; j4 += 4) {
            float4 p0 = *(float4*)&sc[(qg * 2 + 0) * S + kb + j4];
            float4 p1 = *(float4*)&sc[(qg * 2 + 1) * S + kb + j4];
            float v0 = Ks[(j4 + 0) * KVP + d];
            float v1 = Ks[(j4 + 1) * KVP + d];
            float v2 = Ks[(j4 + 2) * KVP + d];
            float v3 = Ks[(j4 + 3) * KVP + d];
            c0 += p0.x * v0 + p0.y * v1 + p0.z * v2 + p0.w * v3;
            c1 += p1.x * v0 + p1.y * v1 + p1.z * v2 + p1.w * v3;
        }
    }
    g_ctx[(size_t)(b * S + q0 + qg * 2 + 0) * H + h * DH + d] = c0;
    g_ctx[(size_t)(b * S + q0 + qg * 2 + 1) * H + h * DH + d] = c1;
}

// ---------------- residual + LayerNorm(768) ----------------
__global__ __launch_bounds__(256) void ln_kernel(const float* __restrict__ P,
                                                 const float* __restrict__ Xres,
                                                 const float* __restrict__ w,
                                                 const float* __restrict__ bb,
                                                 float* __restrict__ out)
{
    const int tok = blockIdx.x;
    const int t   = threadIdx.x;
    __shared__ float rs[8], rq[8];
    __shared__ float smu, siv;

    float v[3];
    float s = 0.f, sq = 0.f;
#pragma unroll
    for (int i = 0; i < 3; i++) {
        int c = t + i * 256;
        float x = P[(size_t)tok * H + c] + Xres[(size_t)tok * H + c];
        v[i] = x; s += x; sq += x * x;
    }
    for (int o = 16; o; o >>= 1) {
        s  += __shfl_xor_sync(0xffffffffu, s, o);
        sq += __shfl_xor_sync(0xffffffffu, sq, o);
    }
    int wi = t >> 5, ln = t & 31;
    if (ln == 0) { rs[wi] = s; rq[wi] = sq; }
    __syncthreads();
    if (t == 0) {
        float ts = 0.f, tq = 0.f;
#pragma unroll
        for (int i = 0; i < 8; i++) { ts += rs[i]; tq += rq[i]; }
        float mu = ts * (1.f / H);
        smu = mu;
        siv = rsqrtf(tq * (1.f / H) - mu * mu + EPS);
    }
    __syncthreads();
    float mu = smu, iv = siv;
#pragma unroll
    for (int i = 0; i < 3; i++) {
        int c = t + i * 256;
        out[(size_t)tok * H + c] = (v[i] - mu) * iv * w[c] + bb[c];
    }
}

// ---------------- launch ----------------
extern "C" void kernel_launch(void* const* d_in, const int* in_sizes, int n_in,
                              void* d_out, int out_size)
{
    const float* X    = (const float*)d_in[0];
    const float* am   = (const float*)d_in[1];
    const float* Wq   = (const float*)d_in[2];
    const float* bq   = (const float*)d_in[3];
    const float* Wk   = (const float*)d_in[4];
    const float* bk   = (const float*)d_in[5];
    const float* Wv   = (const float*)d_in[6];
    const float* bv   = (const float*)d_in[7];
    const float* Wg1  = (const float*)d_in[8];
    const float* bg1  = (const float*)d_in[9];
    const float* glnw = (const float*)d_in[10];
    const float* glnb = (const float*)d_in[11];
    const float* Wg2  = (const float*)d_in[12];
    const float* bg2  = (const float*)d_in[13];
    const float* Wo   = (const float*)d_in[14];
    const float* bo   = (const float*)d_in[15];
    const float* lnw  = (const float*)d_in[16];
    const float* lnb  = (const float*)d_in[17];

    float* out   = (float*)d_out;
    float* probs = out + (size_t)B * S * H;

    float *Qp, *Kp, *Vp, *Cp, *Pp;
    cudaGetSymbolAddress((void**)&Qp, g_Q);
    cudaGetSymbolAddress((void**)&Kp, g_K);
    cudaGetSymbolAddress((void**)&Vp, g_V);
    cudaGetSymbolAddress((void**)&Cp, g_ctx);
    cudaGetSymbolAddress((void**)&Pp, g_proj);

    dim3 ggemm(H / BN, TOK / BM);
    sgemm_bias<<<ggemm, 256>>>(X, Wq, bq, Qp, TOK, H, H);
    sgemm_bias<<<ggemm, 256>>>(X, Wk, bk, Kp, TOK, H, H);
    sgemm_bias<<<ggemm, 256>>>(X, Wv, bv, Vp, TOK, H, H);

    {
        float* Gp;
        cudaGetSymbolAddress((void**)&Gp, g_gates);
        gate_kernel<<<TOK / GTOK, 128>>>(X, Wg1, bg1, glnw, glnb, Wg2, bg2, Gp);
    }

    size_t att_smem = (size_t)(QT * S + KT * KVP + QT * 64 + S + QT) * sizeof(float);
    cudaFuncSetAttribute(attn_kernel, cudaFuncAttributeMaxDynamicSharedMemorySize, (int)att_smem);
    dim3 gatt(S / QT, NH, B);
    attn_kernel<<<gatt, 512, att_smem>>>(am, probs);

    sgemm_bias<<<ggemm, 256>>>(Cp, Wo, bo, Pp, TOK, H, H);

    ln_kernel<<<TOK, 256>>>(Pp, X, lnw, lnb, out);
}

// round 4
// speedup vs baseline: 3.0555x; 3.0114x over previous
#include <cuda_runtime.h>
#include <math.h>
#include <stdint.h>

#define B 4
#define S 2048
#define H 768
#define NH 12
#define DH 64
#define WH 128
#define TOK (B*S)
#define EPS 1e-12f

__device__ float g_Q[(size_t)TOK*H];
__device__ float g_K[(size_t)TOK*H];
__device__ float g_V[(size_t)TOK*H];
__device__ float g_ctx[(size_t)TOK*H];
__device__ float g_proj[(size_t)TOK*H];
__device__ float g_gates[(size_t)TOK*NH];

__device__ __forceinline__ uint32_t f2t(float x){
    uint32_t u; asm("cvt.rna.tf32.f32 %0, %1;" : "=r"(u) : "f"(x)); return u;
}
__device__ __forceinline__ float4 cvt4(float4 v){
    return make_float4(__uint_as_float(f2t(v.x)), __uint_as_float(f2t(v.y)),
                       __uint_as_float(f2t(v.z)), __uint_as_float(f2t(v.w)));
}
__device__ __forceinline__ void mma8(float* c, const uint32_t* a, const uint32_t* b){
    asm volatile("mma.sync.aligned.m16n8k8.row.col.f32.tf32.tf32.f32 "
        "{%0,%1,%2,%3}, {%4,%5,%6,%7}, {%8,%9}, {%0,%1,%2,%3};"
        : "+f"(c[0]), "+f"(c[1]), "+f"(c[2]), "+f"(c[3])
        : "r"(a[0]), "r"(a[1]), "r"(a[2]), "r"(a[3]), "r"(b[0]), "r"(b[1]));
}

// ================= tf32 MMA GEMM: C[M,N] = A[M,K] @ W[K,N] + bias =================
#define GBM 128
#define GBN 128
#define GBK 16
#define GST 132

__global__ __launch_bounds__(256) void gemm_tf32(const float* __restrict__ A,
                                                 const float* __restrict__ Wm,
                                                 const float* __restrict__ bias,
                                                 float* __restrict__ C,
                                                 int M, int N, int K)
{
    __shared__ float As[GBK][GST];   // [k][m]
    __shared__ float Bs[GBK][GST];   // [k][n]
    const int t = threadIdx.x, lane = t & 31, w = t >> 5;
    const int wr = w >> 1, wc = w & 1;
    const int m0 = blockIdx.y * GBM, n0 = blockIdx.x * GBN;
    const int qr = lane >> 2, qc = lane & 3;

    float acc[2][8][4];
#pragma unroll
    for (int mt = 0; mt < 2; mt++)
#pragma unroll
        for (int nt = 0; nt < 8; nt++)
#pragma unroll
            for (int i = 0; i < 4; i++) acc[mt][nt][i] = 0.f;

    for (int k0 = 0; k0 < K; k0 += GBK) {
        __syncthreads();
#pragma unroll
        for (int i = 0; i < 2; i++) {
            int idx = t * 2 + i;                 // 0..511 : 128 rows x 4 f4
            int row = idx >> 2, c4 = (idx & 3) * 4;
            float4 v = *(const float4*)&A[(size_t)(m0 + row) * K + k0 + c4];
            As[c4 + 0][row] = __uint_as_float(f2t(v.x));
            As[c4 + 1][row] = __uint_as_float(f2t(v.y));
            As[c4 + 2][row] = __uint_as_float(f2t(v.z));
            As[c4 + 3][row] = __uint_as_float(f2t(v.w));
        }
#pragma unroll
        for (int i = 0; i < 2; i++) {
            int idx = t * 2 + i;                 // 0..511 : 16 k x 32 f4
            int kk = idx >> 5, c4 = (idx & 31) * 4;
            float4 v = *(const float4*)&Wm[(size_t)(k0 + kk) * N + n0 + c4];
            *(float4*)&Bs[kk][c4] = cvt4(v);
        }
        __syncthreads();

#pragma unroll
        for (int ks = 0; ks < 2; ks++) {
            const int kb = ks * 8;
            uint32_t aa[2][4];
#pragma unroll
            for (int mt = 0; mt < 2; mt++) {
                int mb = 32 * wr + 16 * mt;
                aa[mt][0] = __float_as_uint(As[kb + qc][mb + qr]);
                aa[mt][1] = __float_as_uint(As[kb + qc][mb + qr + 8]);
                aa[mt][2] = __float_as_uint(As[kb + qc + 4][mb + qr]);
                aa[mt][3] = __float_as_uint(As[kb + qc + 4][mb + qr + 8]);
            }
#pragma unroll
            for (int nt = 0; nt < 8; nt++) {
                int nb = 64 * wc + 8 * nt;
                uint32_t bb[2];
                bb[0] = __float_as_uint(Bs[kb + qc][nb + qr]);
                bb[1] = __float_as_uint(Bs[kb + qc + 4][nb + qr]);
                mma8(acc[0][nt], aa[0], bb);
                mma8(acc[1][nt], aa[1], bb);
            }
        }
    }

#pragma unroll
    for (int mt = 0; mt < 2; mt++)
#pragma unroll
        for (int nt = 0; nt < 8; nt++) {
            int row = m0 + 32 * wr + 16 * mt + qr;
            int col = n0 + 64 * wc + 8 * nt + 2 * qc;
            float b0 = bias[col], b1 = bias[col + 1];
            float2 v0 = make_float2(acc[mt][nt][0] + b0, acc[mt][nt][1] + b1);
            float2 v1 = make_float2(acc[mt][nt][2] + b0, acc[mt][nt][3] + b1);
            *(float2*)&C[(size_t)row * N + col] = v0;
            *(float2*)&C[(size_t)(row + 8) * N + col] = v1;
        }
}

// ================= gate MLP =================
#define GTOK 8
__global__ __launch_bounds__(128) void gate_kernel(const float* __restrict__ X,
                                                   const float* __restrict__ Wg1,
                                                   const float* __restrict__ bg1,
                                                   const float* __restrict__ glnw,
                                                   const float* __restrict__ glnb,
                                                   const float* __restrict__ Wg2,
                                                   const float* __restrict__ bg2,
                                                   float* __restrict__ gates)
{
    __shared__ float xs[GTOK][H];
    __shared__ float gs[GTOK][WH];
    __shared__ float mu_s[GTOK], iv_s[GTOK];
    const int t = threadIdx.x;
    const int tok0 = blockIdx.x * GTOK;

    for (int id = t; id < GTOK * (H / 4); id += 128) {
        int r = id / (H / 4), c = id % (H / 4);
        *(float4*)&xs[r][c * 4] = *(const float4*)&X[(size_t)(tok0 + r) * H + c * 4];
    }
    __syncthreads();

    float acc[GTOK];
    float b0 = bg1[t];
#pragma unroll
    for (int r = 0; r < GTOK; r++) acc[r] = b0;
#pragma unroll 4
    for (int k = 0; k < H; k++) {
        float w = Wg1[(size_t)k * WH + t];
#pragma unroll
        for (int r = 0; r < GTOK; r++) acc[r] += xs[r][k] * w;
    }
#pragma unroll
    for (int r = 0; r < GTOK; r++) gs[r][t] = acc[r];
    __syncthreads();

    int w = t >> 5, ln = t & 31;
    for (int r = w; r < GTOK; r += 4) {
        float s = 0.f, sq = 0.f;
#pragma unroll
        for (int i = 0; i < 4; i++) { float v = gs[r][ln + 32 * i]; s += v; sq += v * v; }
        for (int o = 16; o; o >>= 1) {
            s  += __shfl_xor_sync(0xffffffffu, s, o);
            sq += __shfl_xor_sync(0xffffffffu, sq, o);
        }
        if (ln == 0) {
            float mu = s * (1.f / WH);
            mu_s[r] = mu;
            iv_s[r] = rsqrtf(sq * (1.f / WH) - mu * mu + EPS);
        }
    }
    __syncthreads();
    float gw = glnw[t], gb = glnb[t];
#pragma unroll
    for (int r = 0; r < GTOK; r++) {
        float y = (gs[r][t] - mu_s[r]) * iv_s[r] * gw + gb;
        gs[r][t] = fmaxf(y, 0.f);
    }
    __syncthreads();
    if (t < GTOK * NH) {
        int r = t / NH, hh = t % NH;
        float s = bg2[hh];
#pragma unroll 4
        for (int k = 0; k < WH; k++) s += gs[r][k] * Wg2[k * NH + hh];
        gates[(size_t)(tok0 + r) * NH + hh] = 1.f / (1.f + __expf(-s));
    }
}

// ================= attention: tf32 MMA, 2-pass exact softmax, QT=64 =================
__global__ __launch_bounds__(512) void attn_tf32(const float* __restrict__ am,
                                                 float* __restrict__ probs)
{
    extern __shared__ float sm[];
    float* Qs   = sm;                 // 64 x 68 (tf32 bits)
    float* Ks   = Qs + 64 * 68;       // 128 x 68
    float* Vs   = Ks + 128 * 68;      // 128 x 68
    float* Ps   = Vs + 128 * 68;      // 64 x 132 (fp32 probs tile)
    float* msk  = Ps + 64 * 132;      // S
    float* gt   = msk + S;            // 64
    float* redM = gt + 64;            // 4 x 64
    float* redS = redM + 256;         // 4 x 64
    float* rowM = redS + 256;         // 64
    float* rowI = rowM + 64;          // 64

    const int t = threadIdx.x, lane = t & 31, w = t >> 5;
    const int wr = w >> 2, wk = w & 3;
    const int qr = lane >> 2, qc = lane & 3;
    const int q0 = blockIdx.x * 64;
    const int h  = blockIdx.y;
    const int b  = blockIdx.z;

    {
        const float* Qg = g_Q + ((size_t)(b * S + q0)) * H + h * DH;
#pragma unroll
        for (int i = 0; i < 2; i++) {
            int idx = t + i * 512;            // 64 rows x 16 f4
            int r = idx >> 4, c4 = (idx & 15) * 4;
            float4 v = *(const float4*)&Qg[(size_t)r * H + c4];
            *(float4*)&Qs[r * 68 + c4] = cvt4(v);
        }
        for (int j = t; j < S; j += 512) msk[j] = (1.f - am[(size_t)b * S + j]) * -10000.f;
        if (t < 64) gt[t] = g_gates[(size_t)(b * S + q0 + t) * NH + h] * 0.125f;
    }
    __syncthreads();

    // resident Q fragments (rows wr*16..+16, full k=64)
    uint32_t qa[8][4];
    {
        int mb = wr * 16;
#pragma unroll
        for (int ks = 0; ks < 8; ks++) {
            int kc = ks * 8 + qc;
            qa[ks][0] = __float_as_uint(Qs[(mb + qr) * 68 + kc]);
            qa[ks][1] = __float_as_uint(Qs[(mb + qr + 8) * 68 + kc]);
            qa[ks][2] = __float_as_uint(Qs[(mb + qr) * 68 + kc + 4]);
            qa[ks][3] = __float_as_uint(Qs[(mb + qr + 8) * 68 + kc + 4]);
        }
    }
    const float g0 = gt[wr * 16 + qr], g1 = gt[wr * 16 + qr + 8];

    const float* Kg = g_K + ((size_t)b * S) * H + h * DH;
    const float* Vg = g_V + ((size_t)b * S) * H + h * DH;

    float m0 = -1e30f, s0 = 0.f, m1 = -1e30f, s1 = 0.f;

    // ---------- pass 1: online max/sum ----------
    for (int kt = 0; kt < S / 128; kt++) {
        __syncthreads();
#pragma unroll
        for (int i = 0; i < 4; i++) {
            int idx = t + i * 512;            // 128 rows x 16 f4
            int r = idx >> 4, c4 = (idx & 15) * 4;
            float4 v = *(const float4*)&Kg[(size_t)(kt * 128 + r) * H + c4];
            *(float4*)&Ks[r * 68 + c4] = cvt4(v);
        }
        __syncthreads();
#pragma unroll
        for (int nt = 0; nt < 4; nt++) {
            int nb = wk * 32 + nt * 8;
            float c[4] = {0.f, 0.f, 0.f, 0.f};
#pragma unroll
            for (int ks = 0; ks < 8; ks++) {
                uint32_t bb[2];
                bb[0] = __float_as_uint(Ks[(nb + qr) * 68 + ks * 8 + qc]);
                bb[1] = __float_as_uint(Ks[(nb + qr) * 68 + ks * 8 + qc + 4]);
                mma8(c, qa[ks], bb);
            }
            int col = kt * 128 + nb + 2 * qc;
            float v00 = c[0] * g0 + msk[col], v01 = c[1] * g0 + msk[col + 1];
            float v10 = c[2] * g1 + msk[col], v11 = c[3] * g1 + msk[col + 1];
            float nm = fmaxf(m0, fmaxf(v00, v01));
            s0 = s0 * __expf(m0 - nm) + __expf(v00 - nm) + __expf(v01 - nm); m0 = nm;
            nm = fmaxf(m1, fmaxf(v10, v11));
            s1 = s1 * __expf(m1 - nm) + __expf(v10 - nm) + __expf(v11 - nm); m1 = nm;
        }
    }
    // reduce lane-quads (cols of same row)
#pragma unroll
    for (int off = 1; off <= 2; off <<= 1) {
        float pm = __shfl_xor_sync(0xffffffffu, m0, off);
        float ps = __shfl_xor_sync(0xffffffffu, s0, off);
        float nm = fmaxf(m0, pm);
        s0 = s0 * __expf(m0 - nm) + ps * __expf(pm - nm); m0 = nm;
        pm = __shfl_xor_sync(0xffffffffu, m1, off);
        ps = __shfl_xor_sync(0xffffffffu, s1, off);
        nm = fmaxf(m1, pm);
        s1 = s1 * __expf(m1 - nm) + ps * __expf(pm - nm); m1 = nm;
    }
    if (qc == 0) {
        redM[wk * 64 + wr * 16 + qr] = m0;  redS[wk * 64 + wr * 16 + qr] = s0;
        redM[wk * 64 + wr * 16 + qr + 8] = m1;  redS[wk * 64 + wr * 16 + qr + 8] = s1;
    }
    __syncthreads();
    if (t < 64) {
        float m = redM[t];
#pragma unroll
        for (int i = 1; i < 4; i++) m = fmaxf(m, redM[i * 64 + t]);
        float s = 0.f;
#pragma unroll
        for (int i = 0; i < 4; i++) s += redS[i * 64 + t] * __expf(redM[i * 64 + t] - m);
        rowM[t] = m; rowI[t] = 1.f / s;
    }
    __syncthreads();
    const float M0 = rowM[wr * 16 + qr], I0 = rowI[wr * 16 + qr];
    const float M1 = rowM[wr * 16 + qr + 8], I1 = rowI[wr * 16 + qr + 8];

    // ---------- pass 2: probs + PV ----------
    float cacc[2][4] = {{0.f,0.f,0.f,0.f},{0.f,0.f,0.f,0.f}};
    for (int kt = 0; kt < S / 128; kt++) {
        __syncthreads();
#pragma unroll
        for (int i = 0; i < 8; i++) {
            int idx = t + i * 512;            // 0..4095 : K tile then V tile
            int r = (idx >> 4) & 127, c4 = (idx & 15) * 4;
            const float* src = (i < 4) ? Kg : Vg;
            float* dst = (i < 4) ? Ks : Vs;
            float4 v = *(const float4*)&src[(size_t)(kt * 128 + r) * H + c4];
            *(float4*)&dst[r * 68 + c4] = cvt4(v);
        }
        __syncthreads();
#pragma unroll
        for (int nt = 0; nt < 4; nt++) {
            int nb = wk * 32 + nt * 8;
            float c[4] = {0.f, 0.f, 0.f, 0.f};
#pragma unroll
            for (int ks = 0; ks < 8; ks++) {
                uint32_t bb[2];
                bb[0] = __float_as_uint(Ks[(nb + qr) * 68 + ks * 8 + qc]);
                bb[1] = __float_as_uint(Ks[(nb + qr) * 68 + ks * 8 + qc + 4]);
                mma8(c, qa[ks], bb);
            }
            int lc = nb + 2 * qc;
            int col = kt * 128 + lc;
            float p00 = __expf(c[0] * g0 + msk[col]     - M0) * I0;
            float p01 = __expf(c[1] * g0 + msk[col + 1] - M0) * I0;
            float p10 = __expf(c[2] * g1 + msk[col]     - M1) * I1;
            float p11 = __expf(c[3] * g1 + msk[col + 1] - M1) * I1;
            Ps[(wr * 16 + qr) * 132 + lc] = p00;
            Ps[(wr * 16 + qr) * 132 + lc + 1] = p01;
            Ps[(wr * 16 + qr + 8) * 132 + lc] = p10;
            Ps[(wr * 16 + qr + 8) * 132 + lc + 1] = p11;
        }
        __syncthreads();
        // coalesced probs write
        {
            float* pout = probs + (((size_t)b * NH + h) * S + q0) * S + (size_t)kt * 128;
#pragma unroll
            for (int i = 0; i < 4; i++) {
                int idx = t + i * 512;        // 64 rows x 32 f4
                int r = idx >> 5, c4 = (idx & 31) * 4;
                *(float4*)&pout[(size_t)r * S + c4] = *(float4*)&Ps[r * 132 + c4];
            }
        }
        // PV mma: ctx += P(64xk128) @ V(k128x64)
#pragma unroll
        for (int ks = 0; ks < 16; ks++) {
            int kc = ks * 8 + qc;
            uint32_t aa[4];
            aa[0] = f2t(Ps[(wr * 16 + qr) * 132 + kc]);
            aa[1] = f2t(Ps[(wr * 16 + qr + 8) * 132 + kc]);
            aa[2] = f2t(Ps[(wr * 16 + qr) * 132 + kc + 4]);
            aa[3] = f2t(Ps[(wr * 16 + qr + 8) * 132 + kc + 4]);
#pragma unroll
            for (int j = 0; j < 2; j++) {
                int nb = (wk * 2 + j) * 8;
                uint32_t bb[2];
                bb[0] = __float_as_uint(Vs[(ks * 8 + qc) * 68 + nb + qr]);
                bb[1] = __float_as_uint(Vs[(ks * 8 + qc + 4) * 68 + nb + qr]);
                mma8(cacc[j], aa, bb);
            }
        }
    }
    // ctx out
#pragma unroll
    for (int j = 0; j < 2; j++) {
        int nb = (wk * 2 + j) * 8;
        size_t row = (size_t)b * S + q0 + wr * 16 + qr;
        int col = h * DH + nb + 2 * qc;
        *(float2*)&g_ctx[row * H + col] = make_float2(cacc[j][0], cacc[j][1]);
        *(float2*)&g_ctx[(row + 8) * H + col] = make_float2(cacc[j][2], cacc[j][3]);
    }
}

// ================= residual + LayerNorm(768) =================
__global__ __launch_bounds__(256) void ln_kernel(const float* __restrict__ P,
                                                 const float* __restrict__ Xres,
                                                 const float* __restrict__ wgt,
                                                 const float* __restrict__ bb,
                                                 float* __restrict__ out)
{
    const int tok = blockIdx.x;
    const int t = threadIdx.x;
    __shared__ float rs[8], rq[8];
    __shared__ float smu, siv;

    float v[3];
    float s = 0.f, sq = 0.f;
#pragma unroll
    for (int i = 0; i < 3; i++) {
        int c = t + i * 256;
        float x = P[(size_t)tok * H + c] + Xres[(size_t)tok * H + c];
        v[i] = x; s += x; sq += x * x;
    }
    for (int o = 16; o; o >>= 1) {
        s  += __shfl_xor_sync(0xffffffffu, s, o);
        sq += __shfl_xor_sync(0xffffffffu, sq, o);
    }
    int wi = t >> 5, ln = t & 31;
    if (ln == 0) { rs[wi] = s; rq[wi] = sq; }
    __syncthreads();
    if (t == 0) {
        float ts = 0.f, tq = 0.f;
#pragma unroll
        for (int i = 0; i < 8; i++) { ts += rs[i]; tq += rq[i]; }
        float mu = ts * (1.f / H);
        smu = mu;
        siv = rsqrtf(tq * (1.f / H) - mu * mu + EPS);
    }
    __syncthreads();
    float mu = smu, iv = siv;
#pragma unroll
    for (int i = 0; i < 3; i++) {
        int c = t + i * 256;
        out[(size_t)tok * H + c] = (v[i] - mu) * iv * wgt[c] + bb[c];
    }
}

// ================= launch =================
extern "C" void kernel_launch(void* const* d_in, const int* in_sizes, int n_in,
                              void* d_out, int out_size)
{
    const float* X    = (const float*)d_in[0];
    const float* am   = (const float*)d_in[1];
    const float* Wq   = (const float*)d_in[2];
    const float* bq   = (const float*)d_in[3];
    const float* Wk   = (const float*)d_in[4];
    const float* bk   = (const float*)d_in[5];
    const float* Wv   = (const float*)d_in[6];
    const float* bv   = (const float*)d_in[7];
    const float* Wg1  = (const float*)d_in[8];
    const float* bg1  = (const float*)d_in[9];
    const float* glnw = (const float*)d_in[10];
    const float* glnb = (const float*)d_in[11];
    const float* Wg2  = (const float*)d_in[12];
    const float* bg2  = (const float*)d_in[13];
    const float* Wo   = (const float*)d_in[14];
    const float* bo   = (const float*)d_in[15];
    const float* lnw  = (const float*)d_in[16];
    const float* lnb  = (const float*)d_in[17];

    float* out   = (float*)d_out;
    float* probs = out + (size_t)B * S * H;

    float *Qp, *Kp, *Vp, *Cp, *Pp, *Gp;
    cudaGetSymbolAddress((void**)&Qp, g_Q);
    cudaGetSymbolAddress((void**)&Kp, g_K);
    cudaGetSymbolAddress((void**)&Vp, g_V);
    cudaGetSymbolAddress((void**)&Cp, g_ctx);
    cudaGetSymbolAddress((void**)&Pp, g_proj);
    cudaGetSymbolAddress((void**)&Gp, g_gates);

    dim3 ggemm(H / GBN, TOK / GBM);
    gemm_tf32<<<ggemm, 256>>>(X, Wq, bq, Qp, TOK, H, H);
    gemm_tf32<<<ggemm, 256>>>(X, Wk, bk, Kp, TOK, H, H);
    gemm_tf32<<<ggemm, 256>>>(X, Wv, bv, Vp, TOK, H, H);

    gate_kernel<<<TOK / GTOK, 128>>>(X, Wg1, bg1, glnw, glnb, Wg2, bg2, Gp);

    size_t att_smem = (size_t)(64*68 + 128*68*2 + 64*132 + S + 64 + 256 + 256 + 64 + 64) * sizeof(float);
    cudaFuncSetAttribute(attn_tf32, cudaFuncAttributeMaxDynamicSharedMemorySize, (int)att_smem);
    dim3 gatt(S / 64, NH, B);
    attn_tf32<<<gatt, 512, att_smem>>>(am, probs);

    gemm_tf32<<<ggemm, 256>>>(Cp, Wo, bo, Pp, TOK, H, H);

    ln_kernel<<<TOK, 256>>>(Pp, X, lnw, lnb, out);
}

// round 5
// speedup vs baseline: 3.6611x; 1.1982x over previous
#include <cuda_runtime.h>
#include <math.h>
#include <stdint.h>

#define B 4
#define S 2048
#define H 768
#define NH 12
#define DH 64
#define WH 128
#define TOK (B*S)
#define EPS 1e-12f

__device__ float g_Q[(size_t)TOK*H];
__device__ float g_K[(size_t)TOK*H];
__device__ float g_V[(size_t)TOK*H];
__device__ float g_ctx[(size_t)TOK*H];
__device__ float g_proj[(size_t)TOK*H];
__device__ float g_g1[(size_t)TOK*WH];
__device__ float g_gates[(size_t)TOK*NH];

__device__ __forceinline__ void cpa16(void* dst, const void* src){
    uint32_t d = (uint32_t)__cvta_generic_to_shared(dst);
    asm volatile("cp.async.ca.shared.global [%0], [%1], 16;" :: "r"(d), "l"(src));
}
#define CPA_COMMIT() asm volatile("cp.async.commit_group;" ::: "memory")
#define CPA_WAIT0()  asm volatile("cp.async.wait_group 0;" ::: "memory")
#define CPA_WAIT1()  asm volatile("cp.async.wait_group 1;" ::: "memory")

__device__ __forceinline__ void mma8(float* c, const uint32_t* a, const uint32_t* b){
    asm volatile("mma.sync.aligned.m16n8k8.row.col.f32.tf32.tf32.f32 "
        "{%0,%1,%2,%3}, {%4,%5,%6,%7}, {%8,%9}, {%0,%1,%2,%3};"
        : "+f"(c[0]), "+f"(c[1]), "+f"(c[2]), "+f"(c[3])
        : "r"(a[0]), "r"(a[1]), "r"(a[2]), "r"(a[3]), "r"(b[0]), "r"(b[1]));
}
#define F2U __float_as_uint

// ============ tf32 GEMM, cp.async double-buffered: C = A[M,K]@W[K,N] + bias ============
#define GBM 128
#define GBN 128
#define GBK 16

__global__ __launch_bounds__(256) void gemm_tf32(const float* __restrict__ A,
                                                 const float* __restrict__ Wm,
                                                 const float* __restrict__ bias,
                                                 float* __restrict__ C,
                                                 int M, int N, int K)
{
    __shared__ float As[2][GBM][20];    // [m][k] untransposed, pad 20
    __shared__ float Bs[2][GBK][136];   // [k][n], pad 136
    const int t = threadIdx.x, lane = t & 31, w = t >> 5;
    const int wr = w >> 1, wc = w & 1;
    const int m0 = blockIdx.y * GBM, n0 = blockIdx.x * GBN;
    const int qr = lane >> 2, qc = lane & 3;
    const int NIT = K / GBK;

    float acc[2][8][4];
#pragma unroll
    for (int mt = 0; mt < 2; mt++)
#pragma unroll
        for (int nt = 0; nt < 8; nt++)
#pragma unroll
            for (int i = 0; i < 4; i++) acc[mt][nt][i] = 0.f;

    auto issue = [&](int k0, int buf){
#pragma unroll
        for (int i = 0; i < 2; i++) {
            int idx = t * 2 + i;
            int row = idx >> 2, c4 = (idx & 3) * 4;           // A: 128 rows x 16
            cpa16(&As[buf][row][c4], &A[(size_t)(m0 + row) * K + k0 + c4]);
            int kk = idx >> 5, c42 = (idx & 31) * 4;          // B: 16 k x 128
            cpa16(&Bs[buf][kk][c42], &Wm[(size_t)(k0 + kk) * N + n0 + c42]);
        }
    };

    issue(0, 0); CPA_COMMIT();

    for (int i = 0; i < NIT; i++) {
        if (i + 1 < NIT) { issue((i + 1) * GBK, (i + 1) & 1); CPA_COMMIT(); CPA_WAIT1(); }
        else             { CPA_WAIT0(); }
        __syncthreads();
        const int buf = i & 1;
#pragma unroll
        for (int ks = 0; ks < 2; ks++) {
            const int kb = ks * 8;
            uint32_t aa[2][4];
#pragma unroll
            for (int mt = 0; mt < 2; mt++) {
                int mb = 32 * wr + 16 * mt;
                aa[mt][0] = F2U(As[buf][mb + qr][kb + qc]);
                aa[mt][1] = F2U(As[buf][mb + qr + 8][kb + qc]);
                aa[mt][2] = F2U(As[buf][mb + qr][kb + qc + 4]);
                aa[mt][3] = F2U(As[buf][mb + qr + 8][kb + qc + 4]);
            }
#pragma unroll
            for (int nt = 0; nt < 8; nt++) {
                int nb = 64 * wc + 8 * nt;
                uint32_t bb[2];
                bb[0] = F2U(Bs[buf][kb + qc][nb + qr]);
                bb[1] = F2U(Bs[buf][kb + qc + 4][nb + qr]);
                mma8(acc[0][nt], aa[0], bb);
                mma8(acc[1][nt], aa[1], bb);
            }
        }
        __syncthreads();
    }

#pragma unroll
    for (int mt = 0; mt < 2; mt++)
#pragma unroll
        for (int nt = 0; nt < 8; nt++) {
            int row = m0 + 32 * wr + 16 * mt + qr;
            int col = n0 + 64 * wc + 8 * nt + 2 * qc;
            float b0 = bias[col], b1 = bias[col + 1];
            *(float2*)&C[(size_t)row * N + col] = make_float2(acc[mt][nt][0] + b0, acc[mt][nt][1] + b1);
            *(float2*)&C[(size_t)(row + 8) * N + col] = make_float2(acc[mt][nt][2] + b0, acc[mt][nt][3] + b1);
        }
}

// ============ gate stage 2: LN(128) -> relu -> @Wg2 + bg2 -> sigmoid ============
__global__ __launch_bounds__(256) void gate2_kernel(const float* __restrict__ g1,
                                                    const float* __restrict__ glnw,
                                                    const float* __restrict__ glnb,
                                                    const float* __restrict__ Wg2,
                                                    const float* __restrict__ bg2,
                                                    float* __restrict__ gates)
{
    __shared__ float W2s[WH * NH];
    __shared__ float ys[8][WH + 4];
    const int t = threadIdx.x, w = t >> 5, ln = t & 31;
    const int tok = blockIdx.x * 8 + w;

    for (int i = t; i < WH * NH; i += 256) W2s[i] = Wg2[i];
    __syncthreads();

    float4 x = *(const float4*)&g1[(size_t)tok * WH + ln * 4];
    float s  = x.x + x.y + x.z + x.w;
    float sq = x.x*x.x + x.y*x.y + x.z*x.z + x.w*x.w;
#pragma unroll
    for (int o = 16; o; o >>= 1) {
        s  += __shfl_xor_sync(0xffffffffu, s, o);
        sq += __shfl_xor_sync(0xffffffffu, sq, o);
    }
    float mu = s * (1.f / WH);
    float iv = rsqrtf(sq * (1.f / WH) - mu * mu + EPS);
    float4 wv = *(const float4*)&glnw[ln * 4];
    float4 bv = *(const float4*)&glnb[ln * 4];
    float4 y;
    y.x = fmaxf((x.x - mu) * iv * wv.x + bv.x, 0.f);
    y.y = fmaxf((x.y - mu) * iv * wv.y + bv.y, 0.f);
    y.z = fmaxf((x.z - mu) * iv * wv.z + bv.z, 0.f);
    y.w = fmaxf((x.w - mu) * iv * wv.w + bv.w, 0.f);
    *(float4*)&ys[w][ln * 4] = y;
    __syncwarp();
    if (ln < NH) {
        float acc = bg2[ln];
#pragma unroll 4
        for (int k = 0; k < WH; k++) acc += ys[w][k] * W2s[k * NH + ln];
        gates[(size_t)tok * NH + ln] = 1.f / (1.f + __expf(-acc));
    }
}

// ============ attention: tf32 MMA, cp.async staging, 2-pass exact softmax ============
__global__ __launch_bounds__(512) void attn_tf32(const float* __restrict__ am,
                                                 float* __restrict__ probs)
{
    extern __shared__ float sm[];
    float* Qs   = sm;                  // 64 x 68
    float* Ks   = Qs + 64 * 68;        // 128 x 68
    float* Vs   = Ks + 128 * 68;       // 128 x 72
    float* Ps   = Vs + 128 * 72;       // 64 x 132
    float* msk  = Ps + 64 * 132;       // S
    float* gt   = msk + S;             // 64
    float* redM = gt + 64;             // 4 x 64
    float* redS = redM + 256;          // 4 x 64
    float* rowM = redS + 256;          // 64
    float* rowI = rowM + 64;           // 64

    const int t = threadIdx.x, lane = t & 31, w = t >> 5;
    const int wr = w >> 2, wk = w & 3;
    const int qr = lane >> 2, qc = lane & 3;
    const int q0 = blockIdx.x * 64;
    const int h  = blockIdx.y;
    const int b  = blockIdx.z;

    const float* Qg = g_Q + ((size_t)(b * S + q0)) * H + h * DH;
    const float* Kg = g_K + ((size_t)b * S) * H + h * DH;
    const float* Vg = g_V + ((size_t)b * S) * H + h * DH;

    {
#pragma unroll
        for (int i = 0; i < 2; i++) {
            int idx = t + i * 512;             // 64 rows x 16 f4
            int r = idx >> 4, c4 = (idx & 15) * 4;
            cpa16(&Qs[r * 68 + c4], &Qg[(size_t)r * H + c4]);
        }
        CPA_COMMIT();
        for (int j = t; j < S; j += 512) msk[j] = (1.f - am[(size_t)b * S + j]) * -10000.f;
        if (t < 64) gt[t] = g_gates[(size_t)(b * S + q0 + t) * NH + h] * 0.125f;
        CPA_WAIT0();
    }
    __syncthreads();

    uint32_t qa[8][4];
    {
        int mb = wr * 16;
#pragma unroll
        for (int ks = 0; ks < 8; ks++) {
            int kc = ks * 8 + qc;
            qa[ks][0] = F2U(Qs[(mb + qr) * 68 + kc]);
            qa[ks][1] = F2U(Qs[(mb + qr + 8) * 68 + kc]);
            qa[ks][2] = F2U(Qs[(mb + qr) * 68 + kc + 4]);
            qa[ks][3] = F2U(Qs[(mb + qr + 8) * 68 + kc + 4]);
        }
    }
    const float g0 = gt[wr * 16 + qr], g1v = gt[wr * 16 + qr + 8];

    float m0 = -1e30f, s0 = 0.f, m1 = -1e30f, s1 = 0.f;

    // ---------- pass 1: row max / sum ----------
    for (int kt = 0; kt < S / 128; kt++) {
        __syncthreads();
#pragma unroll
        for (int i = 0; i < 4; i++) {
            int idx = t + i * 512;
            int r = idx >> 4, c4 = (idx & 15) * 4;
            cpa16(&Ks[r * 68 + c4], &Kg[(size_t)(kt * 128 + r) * H + c4]);
        }
        CPA_COMMIT(); CPA_WAIT0();
        __syncthreads();

        float v0[8], v1[8];
#pragma unroll
        for (int nt = 0; nt < 4; nt++) {
            int nb = wk * 32 + nt * 8;
            float c[4] = {0.f, 0.f, 0.f, 0.f};
#pragma unroll
            for (int ks = 0; ks < 8; ks++) {
                uint32_t bb[2];
                bb[0] = F2U(Ks[(nb + qr) * 68 + ks * 8 + qc]);
                bb[1] = F2U(Ks[(nb + qr) * 68 + ks * 8 + qc + 4]);
                mma8(c, qa[ks], bb);
            }
            int col = kt * 128 + nb + 2 * qc;
            v0[nt * 2]     = c[0] * g0  + msk[col];
            v0[nt * 2 + 1] = c[1] * g0  + msk[col + 1];
            v1[nt * 2]     = c[2] * g1v + msk[col];
            v1[nt * 2 + 1] = c[3] * g1v + msk[col + 1];
        }
        float tm0 = v0[0], tm1 = v1[0];
#pragma unroll
        for (int i = 1; i < 8; i++) { tm0 = fmaxf(tm0, v0[i]); tm1 = fmaxf(tm1, v1[i]); }
        float nm0 = fmaxf(m0, tm0), nm1 = fmaxf(m1, tm1);
        float a0 = 0.f, a1 = 0.f;
#pragma unroll
        for (int i = 0; i < 8; i++) { a0 += __expf(v0[i] - nm0); a1 += __expf(v1[i] - nm1); }
        s0 = s0 * __expf(m0 - nm0) + a0; m0 = nm0;
        s1 = s1 * __expf(m1 - nm1) + a1; m1 = nm1;
    }
#pragma unroll
    for (int off = 1; off <= 2; off <<= 1) {
        float pm = __shfl_xor_sync(0xffffffffu, m0, off);
        float ps = __shfl_xor_sync(0xffffffffu, s0, off);
        float nm = fmaxf(m0, pm);
        s0 = s0 * __expf(m0 - nm) + ps * __expf(pm - nm); m0 = nm;
        pm = __shfl_xor_sync(0xffffffffu, m1, off);
        ps = __shfl_xor_sync(0xffffffffu, s1, off);
        nm = fmaxf(m1, pm);
        s1 = s1 * __expf(m1 - nm) + ps * __expf(pm - nm); m1 = nm;
    }
    if (qc == 0) {
        redM[wk * 64 + wr * 16 + qr] = m0;      redS[wk * 64 + wr * 16 + qr] = s0;
        redM[wk * 64 + wr * 16 + qr + 8] = m1;  redS[wk * 64 + wr * 16 + qr + 8] = s1;
    }
    __syncthreads();
    if (t < 64) {
        float m = redM[t];
#pragma unroll
        for (int i = 1; i < 4; i++) m = fmaxf(m, redM[i * 64 + t]);
        float s = 0.f;
#pragma unroll
        for (int i = 0; i < 4; i++) s += redS[i * 64 + t] * __expf(redM[i * 64 + t] - m);
        rowM[t] = m; rowI[t] = 1.f / s;
    }
    __syncthreads();
    const float M0 = rowM[wr * 16 + qr], I0 = rowI[wr * 16 + qr];
    const float M1 = rowM[wr * 16 + qr + 8], I1 = rowI[wr * 16 + qr + 8];

    // ---------- pass 2: probs + PV ----------
    float cacc[2][4] = {{0.f,0.f,0.f,0.f},{0.f,0.f,0.f,0.f}};
    for (int kt = 0; kt < S / 128; kt++) {
        __syncthreads();
#pragma unroll
        for (int i = 0; i < 4; i++) {
            int idx = t + i * 512;
            int r = idx >> 4, c4 = (idx & 15) * 4;
            cpa16(&Ks[r * 68 + c4], &Kg[(size_t)(kt * 128 + r) * H + c4]);
            cpa16(&Vs[r * 72 + c4], &Vg[(size_t)(kt * 128 + r) * H + c4]);
        }
        CPA_COMMIT(); CPA_WAIT0();
        __syncthreads();

#pragma unroll
        for (int nt = 0; nt < 4; nt++) {
            int nb = wk * 32 + nt * 8;
            float c[4] = {0.f, 0.f, 0.f, 0.f};
#pragma unroll
            for (int ks = 0; ks < 8; ks++) {
                uint32_t bb[2];
                bb[0] = F2U(Ks[(nb + qr) * 68 + ks * 8 + qc]);
                bb[1] = F2U(Ks[(nb + qr) * 68 + ks * 8 + qc + 4]);
                mma8(c, qa[ks], bb);
            }
            int lc = nb + 2 * qc;
            int col = kt * 128 + lc;
            Ps[(wr * 16 + qr) * 132 + lc]         = __expf(c[0] * g0  + msk[col]     - M0) * I0;
            Ps[(wr * 16 + qr) * 132 + lc + 1]     = __expf(c[1] * g0  + msk[col + 1] - M0) * I0;
            Ps[(wr * 16 + qr + 8) * 132 + lc]     = __expf(c[2] * g1v + msk[col]     - M1) * I1;
            Ps[(wr * 16 + qr + 8) * 132 + lc + 1] = __expf(c[3] * g1v + msk[col + 1] - M1) * I1;
        }
        __syncthreads();
        {
            float* pout = probs + (((size_t)b * NH + h) * S + q0) * S + (size_t)kt * 128;
#pragma unroll
            for (int i = 0; i < 4; i++) {
                int idx = t + i * 512;
                int r = idx >> 5, c4 = (idx & 31) * 4;
                *(float4*)&pout[(size_t)r * S + c4] = *(float4*)&Ps[r * 132 + c4];
            }
        }
#pragma unroll
        for (int ks = 0; ks < 16; ks++) {
            int kc = ks * 8 + qc;
            uint32_t aa[4];
            aa[0] = F2U(Ps[(wr * 16 + qr) * 132 + kc]);
            aa[1] = F2U(Ps[(wr * 16 + qr + 8) * 132 + kc]);
            aa[2] = F2U(Ps[(wr * 16 + qr) * 132 + kc + 4]);
            aa[3] = F2U(Ps[(wr * 16 + qr + 8) * 132 + kc + 4]);
#pragma unroll
            for (int j = 0; j < 2; j++) {
                int nb = (wk * 2 + j) * 8;
                uint32_t bb[2];
                bb[0] = F2U(Vs[(ks * 8 + qc) * 72 + nb + qr]);
                bb[1] = F2U(Vs[(ks * 8 + qc + 4) * 72 + nb + qr]);
                mma8(cacc[j], aa, bb);
            }
        }
    }
#pragma unroll
    for (int j = 0; j < 2; j++) {
        int nb = (wk * 2 + j) * 8;
        size_t row = (size_t)b * S + q0 + wr * 16 + qr;
        int col = h * DH + nb + 2 * qc;
        *(float2*)&g_ctx[row * H + col] = make_float2(cacc[j][0], cacc[j][1]);
        *(float2*)&g_ctx[(row + 8) * H + col] = make_float2(cacc[j][2], cacc[j][3]);
    }
}

// ============ residual + LayerNorm(768) ============
__global__ __launch_bounds__(256) void ln_kernel(const float* __restrict__ P,
                                                 const float* __restrict__ Xres,
                                                 const float* __restrict__ wgt,
                                                 const float* __restrict__ bb,
                                                 float* __restrict__ out)
{
    const int tok = blockIdx.x;
    const int t = threadIdx.x;
    __shared__ float rs[8], rq[8];
    __shared__ float smu, siv;

    float v[3];
    float s = 0.f, sq = 0.f;
#pragma unroll
    for (int i = 0; i < 3; i++) {
        int c = t + i * 256;
        float x = P[(size_t)tok * H + c] + Xres[(size_t)tok * H + c];
        v[i] = x; s += x; sq += x * x;
    }
    for (int o = 16; o; o >>= 1) {
        s  += __shfl_xor_sync(0xffffffffu, s, o);
        sq += __shfl_xor_sync(0xffffffffu, sq, o);
    }
    int wi = t >> 5, ln = t & 31;
    if (ln == 0) { rs[wi] = s; rq[wi] = sq; }
    __syncthreads();
    if (t == 0) {
        float ts = 0.f, tq = 0.f;
#pragma unroll
        for (int i = 0; i < 8; i++) { ts += rs[i]; tq += rq[i]; }
        float mu = ts * (1.f / H);
        smu = mu;
        siv = rsqrtf(tq * (1.f / H) - mu * mu + EPS);
    }
    __syncthreads();
    float mu = smu, iv = siv;
#pragma unroll
    for (int i = 0; i < 3; i++) {
        int c = t + i * 256;
        out[(size_t)tok * H + c] = (v[i] - mu) * iv * wgt[c] + bb[c];
    }
}

// ============ launch ============
extern "C" void kernel_launch(void* const* d_in, const int* in_sizes, int n_in,
                              void* d_out, int out_size)
{
    const float* X    = (const float*)d_in[0];
    const float* am   = (const float*)d_in[1];
    const float* Wq   = (const float*)d_in[2];
    const float* bq   = (const float*)d_in[3];
    const float* Wk   = (const float*)d_in[4];
    const float* bk   = (const float*)d_in[5];
    const float* Wv   = (const float*)d_in[6];
    const float* bv   = (const float*)d_in[7];
    const float* Wg1  = (const float*)d_in[8];
    const float* bg1  = (const float*)d_in[9];
    const float* glnw = (const float*)d_in[10];
    const float* glnb = (const float*)d_in[11];
    const float* Wg2  = (const float*)d_in[12];
    const float* bg2  = (const float*)d_in[13];
    const float* Wo   = (const float*)d_in[14];
    const float* bo   = (const float*)d_in[15];
    const float* lnw  = (const float*)d_in[16];
    const float* lnb  = (const float*)d_in[17];

    float* out   = (float*)d_out;
    float* probs = out + (size_t)B * S * H;

    float *Qp, *Kp, *Vp, *Cp, *Pp, *G1p, *Gp;
    cudaGetSymbolAddress((void**)&Qp, g_Q);
    cudaGetSymbolAddress((void**)&Kp, g_K);
    cudaGetSymbolAddress((void**)&Vp, g_V);
    cudaGetSymbolAddress((void**)&Cp, g_ctx);
    cudaGetSymbolAddress((void**)&Pp, g_proj);
    cudaGetSymbolAddress((void**)&G1p, g_g1);
    cudaGetSymbolAddress((void**)&Gp, g_gates);

    dim3 ggemm(H / GBN, TOK / GBM);
    gemm_tf32<<<ggemm, 256>>>(X, Wq, bq, Qp, TOK, H, H);
    gemm_tf32<<<ggemm, 256>>>(X, Wk, bk, Kp, TOK, H, H);
    gemm_tf32<<<ggemm, 256>>>(X, Wv, bv, Vp, TOK, H, H);

    dim3 ggate(WH / GBN, TOK / GBM);
    gemm_tf32<<<ggate, 256>>>(X, Wg1, bg1, G1p, TOK, WH, H);
    gate2_kernel<<<TOK / 8, 256>>>(G1p, glnw, glnb, Wg2, bg2, Gp);

    size_t att_smem = (size_t)(64*68 + 128*68 + 128*72 + 64*132 + S + 64 + 256 + 256 + 64 + 64) * sizeof(float);
    cudaFuncSetAttribute(attn_tf32, cudaFuncAttributeMaxDynamicSharedMemorySize, (int)att_smem);
    dim3 gatt(S / 64, NH, B);
    attn_tf32<<<gatt, 512, att_smem>>>(am, probs);

    gemm_tf32<<<ggemm, 256>>>(Cp, Wo, bo, Pp, TOK, H, H);

    ln_kernel<<<TOK, 256>>>(Pp, X, lnw, lnb, out);
}